// round 3
// baseline (speedup 1.0000x reference)
#include <cuda_runtime.h>
#include <cuda_bf16.h>
#include <math.h>

// Problem constants (from reference): N=100000, E=1600000, IN=HID=256, H=4, D=64, C=40
#define N_MAX 100000
#define E_MAX 1600000
#define HID   256

// ---------------- static device scratch (no allocs allowed) ----------------
__device__ float g_feat[N_MAX * HID];    // GEMM output per layer (also reused for 40-col output feats)
__device__ float g_bufA[N_MAX * HID];    // ping-pong h buffers
__device__ float g_bufB[N_MAX * HID];
__device__ float g_el[N_MAX * 4];
__device__ float g_er[N_MAX * 4];
__device__ int   g_cnt[N_MAX + 1];
__device__ int   g_rowptr[N_MAX + 1];
__device__ int   g_cursor[N_MAX];
__device__ int   g_csrsrc[E_MAX];

static inline int cdiv(int a, int b) { return (a + b - 1) / b; }

// ---------------- CSR build ----------------
__global__ void k_zero(int* cnt, int n) {
    int i = blockIdx.x * blockDim.x + threadIdx.x;
    if (i < n) cnt[i] = 0;
}

__global__ void k_hist(const int* __restrict__ dst, int* cnt, int E) {
    int e = blockIdx.x * blockDim.x + threadIdx.x;
    if (e < E) atomicAdd(&cnt[dst[e]], 1);
}

__global__ void k_scan(const int* __restrict__ cnt, int* rowptr, int* cursor, int N) {
    __shared__ int sm[1024];
    int t = threadIdx.x;
    int chunk = (N + 1023) >> 10;
    int s0 = t * chunk;
    int s1 = s0 + chunk; if (s1 > N) s1 = N;
    int s = 0;
    for (int i = s0; i < s1 && i < N; i++) s += cnt[i];
    sm[t] = s;
    __syncthreads();
    // inclusive Hillis-Steele scan
    for (int off = 1; off < 1024; off <<= 1) {
        int v = 0;
        if (t >= off) v = sm[t - off];
        __syncthreads();
        sm[t] += v;
        __syncthreads();
    }
    int run = sm[t] - s;  // exclusive prefix
    for (int i = s0; i < s1 && i < N; i++) {
        rowptr[i] = run;
        cursor[i] = run;
        run += cnt[i];
    }
    if (t == 1023) rowptr[N] = sm[1023];
}

__global__ void k_fill(const int* __restrict__ src, const int* __restrict__ dst,
                       int* cursor, int* csr, int E) {
    int e = blockIdx.x * blockDim.x + threadIdx.x;
    if (e < E) {
        int p = atomicAdd(&cursor[dst[e]], 1);
        csr[p] = src[e];
    }
}

// Deterministic ordering: sort each node's incoming-src list (ties are identical
// values, so fp accumulation order becomes bitwise deterministic).
__global__ void k_sortcsr(const int* __restrict__ rowptr, int* csr, int N) {
    int n = blockIdx.x * blockDim.x + threadIdx.x;
    if (n >= N) return;
    int a = rowptr[n], b = rowptr[n + 1];
    for (int i = a + 1; i < b; i++) {
        int v = csr[i];
        int j = i - 1;
        while (j >= a && csr[j] > v) { csr[j + 1] = csr[j]; j--; }
        csr[j + 1] = v;
    }
}

// ---------------- SGEMM: C[N,256] = A[N,256] * B[256,256] ----------------
// BM=128, BN=128, BK=32, 256 threads, 8x8 per-thread tile.
__global__ __launch_bounds__(256) void k_gemm256(const float* __restrict__ A,
                                                 const float* __restrict__ B,
                                                 float* __restrict__ C, int N) {
    __shared__ __align__(16) float As[32 * 128];
    __shared__ __align__(16) float Bs[32 * 128];

    const int tid = threadIdx.x;
    const int tx = tid & 15;       // col group
    const int ty = tid >> 4;       // row group
    const int r0 = blockIdx.x * 128;
    const int c0 = blockIdx.y * 128;

    float acc[8][8];
#pragma unroll
    for (int i = 0; i < 8; i++)
#pragma unroll
        for (int j = 0; j < 8; j++) acc[i][j] = 0.f;

    for (int kt = 0; kt < 256; kt += 32) {
        __syncthreads();
        // load A tile (transposed into As[k][row])
#pragma unroll
        for (int i = 0; i < 4; i++) {
            int id = tid + i * 256;
            int arow = id >> 3, ac4 = id & 7;
            int grow = r0 + arow;
            float4 v = make_float4(0.f, 0.f, 0.f, 0.f);
            if (grow < N) v = *(const float4*)&A[grow * 256 + kt + ac4 * 4];
            As[(ac4 * 4 + 0) * 128 + arow] = v.x;
            As[(ac4 * 4 + 1) * 128 + arow] = v.y;
            As[(ac4 * 4 + 2) * 128 + arow] = v.z;
            As[(ac4 * 4 + 3) * 128 + arow] = v.w;
        }
        // load B tile
#pragma unroll
        for (int i = 0; i < 4; i++) {
            int id = tid + i * 256;
            int brow = id >> 5, bc4 = id & 31;
            float4 v = *(const float4*)&B[(kt + brow) * 256 + c0 + bc4 * 4];
            *(float4*)&Bs[brow * 128 + bc4 * 4] = v;
        }
        __syncthreads();
#pragma unroll
        for (int k = 0; k < 32; k++) {
            float4 a0 = *(const float4*)&As[k * 128 + ty * 8];
            float4 a1 = *(const float4*)&As[k * 128 + ty * 8 + 4];
            float4 b0 = *(const float4*)&Bs[k * 128 + tx * 8];
            float4 b1 = *(const float4*)&Bs[k * 128 + tx * 8 + 4];
            float ar[8] = {a0.x, a0.y, a0.z, a0.w, a1.x, a1.y, a1.z, a1.w};
            float br[8] = {b0.x, b0.y, b0.z, b0.w, b1.x, b1.y, b1.z, b1.w};
#pragma unroll
            for (int i = 0; i < 8; i++)
#pragma unroll
                for (int j = 0; j < 8; j++) acc[i][j] += ar[i] * br[j];
        }
    }

#pragma unroll
    for (int i = 0; i < 8; i++) {
        int r = r0 + ty * 8 + i;
        if (r < N) {
            *(float4*)&C[r * 256 + c0 + tx * 8]     = make_float4(acc[i][0], acc[i][1], acc[i][2], acc[i][3]);
            *(float4*)&C[r * 256 + c0 + tx * 8 + 4] = make_float4(acc[i][4], acc[i][5], acc[i][6], acc[i][7]);
        }
    }
}

// ---------------- small GEMM: C[N,40] = A[N,256] * B[256,40] ----------------
__global__ __launch_bounds__(256) void k_gemm40(const float* __restrict__ A,
                                                const float* __restrict__ B,
                                                float* __restrict__ C, int N) {
    __shared__ float As[128 * 33];
    __shared__ float Ws[32 * 40];

    const int tid = threadIdx.x;
    const int rg = tid >> 3;        // 0..31 -> 4 rows each
    const int cg = tid & 7;         // 0..7  -> 5 cols each
    const int r0 = blockIdx.x * 128;

    float acc[4][5];
#pragma unroll
    for (int i = 0; i < 4; i++)
#pragma unroll
        for (int j = 0; j < 5; j++) acc[i][j] = 0.f;

    for (int kc = 0; kc < 8; kc++) {
        __syncthreads();
        // load A chunk [128][32]
#pragma unroll
        for (int i = 0; i < 4; i++) {
            int id = tid + i * 256;
            int arow = id >> 3, ac4 = id & 7;
            int grow = r0 + arow;
            float4 v = make_float4(0.f, 0.f, 0.f, 0.f);
            if (grow < N) v = *(const float4*)&A[grow * 256 + kc * 32 + ac4 * 4];
            As[arow * 33 + ac4 * 4 + 0] = v.x;
            As[arow * 33 + ac4 * 4 + 1] = v.y;
            As[arow * 33 + ac4 * 4 + 2] = v.z;
            As[arow * 33 + ac4 * 4 + 3] = v.w;
        }
        // load W chunk [32][40] = 1280 floats = 5*256
#pragma unroll
        for (int i = 0; i < 5; i++) {
            int id = tid + i * 256;
            Ws[id] = B[kc * 32 * 40 + id];
        }
        __syncthreads();
#pragma unroll
        for (int k = 0; k < 32; k++) {
            float a_[4];
#pragma unroll
            for (int i = 0; i < 4; i++) a_[i] = As[(rg * 4 + i) * 33 + k];
            float w_[5];
#pragma unroll
            for (int j = 0; j < 5; j++) w_[j] = Ws[k * 40 + cg * 5 + j];
#pragma unroll
            for (int i = 0; i < 4; i++)
#pragma unroll
                for (int j = 0; j < 5; j++) acc[i][j] += a_[i] * w_[j];
        }
    }
#pragma unroll
    for (int i = 0; i < 4; i++) {
        int r = r0 + rg * 4 + i;
        if (r < N) {
#pragma unroll
            for (int j = 0; j < 5; j++) C[r * 40 + cg * 5 + j] = acc[i][j];
        }
    }
}

// ---------------- attention coefficients (hidden layers) ----------------
// one warp per (node, head): el[n,h] = sum_d feat[n,h,d]*al[h,d]; er likewise
__global__ void k_attn(const float* __restrict__ feat, const float* __restrict__ al,
                       const float* __restrict__ ar, float* __restrict__ el,
                       float* __restrict__ er, int N) {
    int w = (blockIdx.x * blockDim.x + threadIdx.x) >> 5;
    int lane = threadIdx.x & 31;
    if (w >= N * 4) return;
    int n = w >> 2, h = w & 3;
    float f1 = feat[n * 256 + h * 64 + lane];
    float f2 = feat[n * 256 + h * 64 + lane + 32];
    float pl = f1 * al[h * 64 + lane] + f2 * al[h * 64 + lane + 32];
    float pr = f1 * ar[h * 64 + lane] + f2 * ar[h * 64 + lane + 32];
#pragma unroll
    for (int o = 16; o; o >>= 1) {
        pl += __shfl_xor_sync(0xffffffffu, pl, o);
        pr += __shfl_xor_sync(0xffffffffu, pr, o);
    }
    if (lane == 0) { el[n * 4 + h] = pl; er[n * 4 + h] = pr; }
}

// ---------------- fused aggregation + bias + ELU + LayerNorm + leaky + residual ----------------
// one warp per destination node
__global__ void k_agg(const float* __restrict__ feat, const float* __restrict__ el,
                      const float* __restrict__ er, const int* __restrict__ rowptr,
                      const int* __restrict__ csr, const float* __restrict__ hin,
                      const float* __restrict__ bias, const float* __restrict__ lng,
                      const float* __restrict__ lnb, float* __restrict__ hout, int N) {
    int w = (blockIdx.x * blockDim.x + threadIdx.x) >> 5;
    int lane = threadIdx.x & 31;
    if (w >= N) return;
    int r0 = rowptr[w], r1 = rowptr[w + 1];
    int deg = r1 - r0;

    float ern0 = er[w * 4 + 0], ern1 = er[w * 4 + 1];
    float ern2 = er[w * 4 + 2], ern3 = er[w * 4 + 3];

    // pass 1: per-head max of leaky(el[src]+er[dst])
    float m0 = -1e30f, m1 = -1e30f, m2 = -1e30f, m3 = -1e30f;
    for (int k = lane; k < deg; k += 32) {
        int s = csr[r0 + k];
        float v;
        v = el[s * 4 + 0] + ern0; v = v >= 0.f ? v : 0.2f * v; m0 = fmaxf(m0, v);
        v = el[s * 4 + 1] + ern1; v = v >= 0.f ? v : 0.2f * v; m1 = fmaxf(m1, v);
        v = el[s * 4 + 2] + ern2; v = v >= 0.f ? v : 0.2f * v; m2 = fmaxf(m2, v);
        v = el[s * 4 + 3] + ern3; v = v >= 0.f ? v : 0.2f * v; m3 = fmaxf(m3, v);
    }
#pragma unroll
    for (int o = 16; o; o >>= 1) {
        m0 = fmaxf(m0, __shfl_xor_sync(0xffffffffu, m0, o));
        m1 = fmaxf(m1, __shfl_xor_sync(0xffffffffu, m1, o));
        m2 = fmaxf(m2, __shfl_xor_sync(0xffffffffu, m2, o));
        m3 = fmaxf(m3, __shfl_xor_sync(0xffffffffu, m3, o));
    }

    // lane owns channels [lane*4 .. lane*4+3] (head ha) and [128+lane*4 ..] (head hb)
    int ha = lane >> 4;            // 0 or 1
    int hb = ha + 2;               // 2 or 3
    float mA = (ha == 0) ? m0 : m1;
    float mB = (ha == 0) ? m2 : m3;
    float eA = (ha == 0) ? ern0 : ern1;
    float eB = (ha == 0) ? ern2 : ern3;

    float4 a0 = make_float4(0.f, 0.f, 0.f, 0.f);
    float4 a1 = make_float4(0.f, 0.f, 0.f, 0.f);
    float sA = 0.f, sB = 0.f;
    const float4* f4 = (const float4*)feat;

    for (int k = 0; k < deg; k++) {
        int s = csr[r0 + k];
        float va = el[s * 4 + ha] + eA; va = va >= 0.f ? va : 0.2f * va;
        float vb = el[s * 4 + hb] + eB; vb = vb >= 0.f ? vb : 0.2f * vb;
        float wa = __expf(va - mA);
        float wb = __expf(vb - mB);
        sA += wa; sB += wb;
        float4 fa = f4[s * 64 + lane];
        float4 fb = f4[s * 64 + 32 + lane];
        a0.x += wa * fa.x; a0.y += wa * fa.y; a0.z += wa * fa.z; a0.w += wa * fa.w;
        a1.x += wb * fb.x; a1.y += wb * fb.y; a1.z += wb * fb.z; a1.w += wb * fb.w;
    }
    float iA = (sA > 0.f) ? 1.f / sA : 0.f;
    float iB = (sB > 0.f) ? 1.f / sB : 0.f;

    float x[8];
    x[0] = a0.x * iA; x[1] = a0.y * iA; x[2] = a0.z * iA; x[3] = a0.w * iA;
    x[4] = a1.x * iB; x[5] = a1.y * iB; x[6] = a1.z * iB; x[7] = a1.w * iB;

    int c0 = lane * 4;
    int c1 = 128 + lane * 4;
#pragma unroll
    for (int u = 0; u < 4; u++) {
        x[u]     += bias[c0 + u];
        x[4 + u] += bias[c1 + u];
        x[u]     = (x[u]     > 0.f) ? x[u]     : expm1f(x[u]);
        x[4 + u] = (x[4 + u] > 0.f) ? x[4 + u] : expm1f(x[4 + u]);
    }

    // LayerNorm over 256 channels held warp-wide (8 per lane)
    float sum = 0.f;
#pragma unroll
    for (int u = 0; u < 8; u++) sum += x[u];
#pragma unroll
    for (int o = 16; o; o >>= 1) sum += __shfl_xor_sync(0xffffffffu, sum, o);
    float mu = sum * (1.f / 256.f);
    float vs = 0.f;
#pragma unroll
    for (int u = 0; u < 8; u++) { float d = x[u] - mu; vs += d * d; }
#pragma unroll
    for (int o = 16; o; o >>= 1) vs += __shfl_xor_sync(0xffffffffu, vs, o);
    float rstd = rsqrtf(vs * (1.f / 256.f) + 1e-5f);

    float4 h0 = ((const float4*)hin)[w * 64 + lane];
    float4 h1 = ((const float4*)hin)[w * 64 + 32 + lane];
    float hr0[4] = {h0.x, h0.y, h0.z, h0.w};
    float hr1[4] = {h1.x, h1.y, h1.z, h1.w};

    float o0[4], o1[4];
#pragma unroll
    for (int u = 0; u < 4; u++) {
        float y = (x[u] - mu) * rstd * lng[c0 + u] + lnb[c0 + u];
        y = (y >= 0.f) ? y : 0.2f * y;
        o0[u] = y + hr0[u];
        float z = (x[4 + u] - mu) * rstd * lng[c1 + u] + lnb[c1 + u];
        z = (z >= 0.f) ? z : 0.2f * z;
        o1[u] = z + hr1[u];
    }
    ((float4*)hout)[w * 64 + lane]      = make_float4(o0[0], o0[1], o0[2], o0[3]);
    ((float4*)hout)[w * 64 + 32 + lane] = make_float4(o1[0], o1[1], o1[2], o1[3]);
}

// ---------------- output layer attention (H=1, C=40) ----------------
__global__ void k_attnO(const float* __restrict__ feat, const float* __restrict__ al,
                        const float* __restrict__ ar, float* __restrict__ el,
                        float* __restrict__ er, int N) {
    int w = (blockIdx.x * blockDim.x + threadIdx.x) >> 5;
    int lane = threadIdx.x & 31;
    if (w >= N) return;
    float pl = 0.f, pr = 0.f;
    float f = feat[w * 40 + lane];
    pl = f * al[lane];
    pr = f * ar[lane];
    if (lane < 8) {
        float f2 = feat[w * 40 + lane + 32];
        pl += f2 * al[lane + 32];
        pr += f2 * ar[lane + 32];
    }
#pragma unroll
    for (int o = 16; o; o >>= 1) {
        pl += __shfl_xor_sync(0xffffffffu, pl, o);
        pr += __shfl_xor_sync(0xffffffffu, pr, o);
    }
    if (lane == 0) { el[w] = pl; er[w] = pr; }
}

// ---------------- output aggregation -> logits [N,40] ----------------
__global__ void k_aggO(const float* __restrict__ feat, const float* __restrict__ el,
                       const float* __restrict__ er, const int* __restrict__ rowptr,
                       const int* __restrict__ csr, const float* __restrict__ bias,
                       float* __restrict__ out, int N) {
    int w = (blockIdx.x * blockDim.x + threadIdx.x) >> 5;
    int lane = threadIdx.x & 31;
    if (w >= N) return;
    int r0 = rowptr[w], r1 = rowptr[w + 1];
    int deg = r1 - r0;
    float ern = er[w];

    float m = -1e30f;
    for (int k = lane; k < deg; k += 32) {
        int s = csr[r0 + k];
        float v = el[s] + ern;
        v = v >= 0.f ? v : 0.2f * v;
        m = fmaxf(m, v);
    }
#pragma unroll
    for (int o = 16; o; o >>= 1) m = fmaxf(m, __shfl_xor_sync(0xffffffffu, m, o));

    float acc0 = 0.f, acc1 = 0.f, ss = 0.f;
    for (int k = 0; k < deg; k++) {
        int s = csr[r0 + k];
        float v = el[s] + ern;
        v = v >= 0.f ? v : 0.2f * v;
        float wgt = __expf(v - m);
        ss += wgt;
        acc0 += wgt * feat[s * 40 + lane];
        if (lane < 8) acc1 += wgt * feat[s * 40 + lane + 32];
    }
    float inv = (ss > 0.f) ? 1.f / ss : 0.f;
    out[w * 40 + lane] = acc0 * inv + bias[lane];
    if (lane < 8) out[w * 40 + lane + 32] = acc1 * inv + bias[lane + 32];
}

// ---------------- launcher ----------------
extern "C" void kernel_launch(void* const* d_in, const int* in_sizes, int n_in,
                              void* d_out, int out_size) {
    const float* x     = (const float*)d_in[0];
    const float* W_h   = (const float*)d_in[1];
    const float* al_h  = (const float*)d_in[2];
    const float* ar_h  = (const float*)d_in[3];
    const float* b_h   = (const float*)d_in[4];
    const float* lng   = (const float*)d_in[5];
    const float* lnb   = (const float*)d_in[6];
    const float* W_o   = (const float*)d_in[7];
    const float* al_o  = (const float*)d_in[8];
    const float* ar_o  = (const float*)d_in[9];
    const float* b_o   = (const float*)d_in[10];
    const int*   esrc  = (const int*)d_in[11];
    const int*   edst  = (const int*)d_in[12];
    float*       out   = (float*)d_out;

    const int N = in_sizes[0] / HID;
    const int E = in_sizes[11];

    float *feat, *bufA, *bufB, *el, *er;
    int *cnt, *rowptr, *cursor, *csr;
    cudaGetSymbolAddress((void**)&feat, g_feat);
    cudaGetSymbolAddress((void**)&bufA, g_bufA);
    cudaGetSymbolAddress((void**)&bufB, g_bufB);
    cudaGetSymbolAddress((void**)&el,   g_el);
    cudaGetSymbolAddress((void**)&er,   g_er);
    cudaGetSymbolAddress((void**)&cnt,    g_cnt);
    cudaGetSymbolAddress((void**)&rowptr, g_rowptr);
    cudaGetSymbolAddress((void**)&cursor, g_cursor);
    cudaGetSymbolAddress((void**)&csr,    g_csrsrc);

    // --- build CSR (per call; deterministic after sort) ---
    k_zero<<<cdiv(N, 256), 256>>>(cnt, N);
    k_hist<<<cdiv(E, 256), 256>>>(edst, cnt, E);
    k_scan<<<1, 1024>>>(cnt, rowptr, cursor, N);
    k_fill<<<cdiv(E, 256), 256>>>(esrc, edst, cursor, csr, E);
    k_sortcsr<<<cdiv(N, 128), 128>>>(rowptr, csr, N);

    const int aggBlocks  = cdiv(N * 32, 256);
    const int attnBlocks = cdiv(N * 4 * 32, 256);
    dim3 gemmGrid(cdiv(N, 128), 2);

    const float* hcur = x;
    float* houts[3] = {bufA, bufB, bufA};
    for (int l = 0; l < 3; l++) {
        k_gemm256<<<gemmGrid, 256>>>(hcur, W_h + l * 256 * 256, feat, N);
        k_attn<<<attnBlocks, 256>>>(feat, al_h + l * 256, ar_h + l * 256, el, er, N);
        k_agg<<<aggBlocks, 256>>>(feat, el, er, rowptr, csr, hcur,
                                  b_h + l * 256, lng + l * 256, lnb + l * 256,
                                  houts[l], N);
        hcur = houts[l];
    }

    // output layer: feat40 = h @ W_o, then single-head GAT, no activation
    k_gemm40<<<cdiv(N, 128), 256>>>(hcur, W_o, feat, N);
    k_attnO<<<cdiv(N * 32, 256), 256>>>(feat, al_o, ar_o, el, er, N);
    k_aggO<<<cdiv(N * 32, 256), 256>>>(feat, el, er, rowptr, csr, b_o, out, N);
}

// round 5
// speedup vs baseline: 1.4195x; 1.4195x over previous
#include <cuda_runtime.h>
#include <cuda_bf16.h>
#include <math.h>
#include <stdint.h>

// Problem constants: N=100000, E=1600000, IN=HID=256, H=4, D=64, C=40
#define N_MAX 100000
#define E_MAX 1600000
#define HID   256

// ---------------- static device scratch (no allocs allowed) ----------------
__device__ float g_feat[N_MAX * HID];
__device__ float g_bufA[N_MAX * HID];
__device__ float g_bufB[N_MAX * HID];
__device__ float g_el[N_MAX * 4];
__device__ float g_er[N_MAX * 4];
__device__ int   g_cnt[N_MAX + 1];
__device__ int   g_rowptr[N_MAX + 1];
__device__ int   g_cursor[N_MAX];
__device__ int   g_csrsrc[E_MAX];
// split-bf16 transposed weights: [3][256(n)][256(k)]
__device__ __nv_bfloat16 g_WhiT[3 * 256 * 256];
__device__ __nv_bfloat16 g_WloT[3 * 256 * 256];

static inline int cdiv(int a, int b) { return (a + b - 1) / b; }

__device__ __forceinline__ uint32_t smem_u32(const void* p) {
    uint32_t a;
    asm("{ .reg .u64 t; cvta.to.shared.u64 t, %1; cvt.u32.u64 %0, t; }" : "=r"(a) : "l"(p));
    return a;
}

#define LDSM4(r, addr)                                                          \
    asm volatile("ldmatrix.sync.aligned.m8n8.x4.shared.b16 {%0,%1,%2,%3}, [%4];" \
                 : "=r"((r)[0]), "=r"((r)[1]), "=r"((r)[2]), "=r"((r)[3])       \
                 : "r"(addr))

#define MMA16816(d, a, b0, b1)                                                  \
    asm volatile(                                                               \
        "mma.sync.aligned.m16n8k16.row.col.f32.bf16.bf16.f32 "                  \
        "{%0,%1,%2,%3}, {%4,%5,%6,%7}, {%8,%9}, {%0,%1,%2,%3};"                 \
        : "+f"((d)[0]), "+f"((d)[1]), "+f"((d)[2]), "+f"((d)[3])                \
        : "r"((a)[0]), "r"((a)[1]), "r"((a)[2]), "r"((a)[3]), "r"(b0), "r"(b1))

// ---------------- CSR build ----------------
__global__ void k_zero(int* cnt, int n) {
    int i = blockIdx.x * blockDim.x + threadIdx.x;
    if (i < n) cnt[i] = 0;
}
__global__ void k_hist(const int* __restrict__ dst, int* cnt, int E) {
    int e = blockIdx.x * blockDim.x + threadIdx.x;
    if (e < E) atomicAdd(&cnt[dst[e]], 1);
}
__global__ void k_scan(const int* __restrict__ cnt, int* rowptr, int* cursor, int N) {
    __shared__ int sm[1024];
    int t = threadIdx.x;
    int chunk = (N + 1023) >> 10;
    int s0 = t * chunk;
    int s1 = s0 + chunk; if (s1 > N) s1 = N;
    int s = 0;
    for (int i = s0; i < s1 && i < N; i++) s += cnt[i];
    sm[t] = s;
    __syncthreads();
    for (int off = 1; off < 1024; off <<= 1) {
        int v = 0;
        if (t >= off) v = sm[t - off];
        __syncthreads();
        sm[t] += v;
        __syncthreads();
    }
    int run = sm[t] - s;
    for (int i = s0; i < s1 && i < N; i++) {
        rowptr[i] = run;
        cursor[i] = run;
        run += cnt[i];
    }
    if (t == 1023) rowptr[N] = sm[1023];
}
__global__ void k_fill(const int* __restrict__ src, const int* __restrict__ dst,
                       int* cursor, int* csr, int E) {
    int e = blockIdx.x * blockDim.x + threadIdx.x;
    if (e < E) {
        int p = atomicAdd(&cursor[dst[e]], 1);
        csr[p] = src[e];
    }
}
__global__ void k_sortcsr(const int* __restrict__ rowptr, int* csr, int N) {
    int n = blockIdx.x * blockDim.x + threadIdx.x;
    if (n >= N) return;
    int a = rowptr[n], b = rowptr[n + 1];
    for (int i = a + 1; i < b; i++) {
        int v = csr[i];
        int j = i - 1;
        while (j >= a && csr[j] > v) { csr[j + 1] = csr[j]; j--; }
        csr[j + 1] = v;
    }
}

// ---------------- weight split/transpose: BT[l][n][k] = split(W[l][k][n]) ----------------
__global__ void k_prepW(const float* __restrict__ W, __nv_bfloat16* __restrict__ hiT,
                        __nv_bfloat16* __restrict__ loT) {
    int i = blockIdx.x * blockDim.x + threadIdx.x;
    if (i >= 3 * 65536) return;
    int l = i >> 16, r = i & 65535;
    int n = r >> 8, k = r & 255;
    float w = W[l * 65536 + k * 256 + n];
    __nv_bfloat16 h = __float2bfloat16(w);
    hiT[i] = h;
    loT[i] = __float2bfloat16(w - __bfloat162float(h));
}

// ---------------- split-bf16 mma.sync GEMM + fused attn-coefficient epilogue -------------
// C[128 x 256] = A[128 x 256] @ W, W as BT[n][k] hi/lo.
// acc += A_hi*B_hi + A_hi*B_lo + A_lo*B_hi  (fp32 accum in registers).
// smem: A tile 128x256 bf16 (64KB) + B tile 256x256 bf16 (128KB) = 192KB.
#define GEMM_SMEM (65536 + 131072)

__global__ __launch_bounds__(256, 1)
void k_gemmMMA(const float* __restrict__ A,
               const __nv_bfloat16* __restrict__ BhiT,
               const __nv_bfloat16* __restrict__ BloT,
               const float* __restrict__ al, const float* __restrict__ ar,
               float* __restrict__ C, float* __restrict__ el, float* __restrict__ er,
               int N) {
    extern __shared__ __align__(128) char smem[];
    char* sA = smem;            // 64KB: [m(128)][k(256)] bf16, row 512B, swizzled
    char* sB = smem + 65536;    // 128KB: [n(256)][k(256)] bf16, row 512B, swizzled

    const int tid  = threadIdx.x;
    const int lane = tid & 31;
    const int wid  = tid >> 5;
    const int wm   = wid >> 2;   // 0..1 : rows [wm*64, +64)
    const int wn   = wid & 3;    // 0..3 : cols [wn*64, +64)  == head wn
    const int r0   = blockIdx.x * 128;

    const uint32_t baseA = smem_u32(sA);
    const uint32_t baseB = smem_u32(sB);
    const uint32_t sw = (uint32_t)(lane & 7) << 4;   // swizzle XOR (m&7 == n&7 == lane&7)

    float acc[4][8][4];
#pragma unroll
    for (int mi = 0; mi < 4; mi++)
#pragma unroll
        for (int ni = 0; ni < 8; ni++)
#pragma unroll
            for (int q = 0; q < 4; q++) acc[mi][ni][q] = 0.f;

    // ldmatrix base offsets (k part added per step, then XOR swizzle)
    uint32_t aoff[4], boff[4];
#pragma unroll
    for (int mi = 0; mi < 4; mi++) {
        int m = wm * 64 + mi * 16 + (lane & 15);
        aoff[mi] = (uint32_t)(m * 512 + ((lane >> 4) << 4));
    }
#pragma unroll
    for (int nj = 0; nj < 4; nj++) {
        int n = wn * 64 + nj * 16 + (lane & 7) + ((lane >> 4) << 3);
        boff[nj] = (uint32_t)(n * 512 + (((lane >> 3) & 1) << 4));
    }

    // passes: 0 = A_hi*B_hi, 1 = A_hi*B_lo (A kept), 2 = A_lo*B_hi
    for (int pass = 0; pass < 3; pass++) {
        if (pass != 1) {
            const bool lo = (pass == 2);
#pragma unroll 4
            for (int i = 0; i < 32; i++) {
                int idx = tid + i * 256;        // 0..8191 float4 chunks
                int m = idx >> 6;
                int kc = idx & 63;              // float4 index within row
                int rowG = r0 + m;
                float4 v = make_float4(0.f, 0.f, 0.f, 0.f);
                if (rowG < N) v = *(const float4*)&A[(size_t)rowG * 256 + kc * 4];
                unsigned short t0, t1, t2, t3;
                if (!lo) {
                    t0 = __bfloat16_as_ushort(__float2bfloat16(v.x));
                    t1 = __bfloat16_as_ushort(__float2bfloat16(v.y));
                    t2 = __bfloat16_as_ushort(__float2bfloat16(v.z));
                    t3 = __bfloat16_as_ushort(__float2bfloat16(v.w));
                } else {
                    __nv_bfloat16 h;
                    h = __float2bfloat16(v.x); t0 = __bfloat16_as_ushort(__float2bfloat16(v.x - __bfloat162float(h)));
                    h = __float2bfloat16(v.y); t1 = __bfloat16_as_ushort(__float2bfloat16(v.y - __bfloat162float(h)));
                    h = __float2bfloat16(v.z); t2 = __bfloat16_as_ushort(__float2bfloat16(v.z - __bfloat162float(h)));
                    h = __float2bfloat16(v.w); t3 = __bfloat16_as_ushort(__float2bfloat16(v.w - __bfloat162float(h)));
                }
                uint32_t u01 = (uint32_t)t0 | ((uint32_t)t1 << 16);
                uint32_t u23 = (uint32_t)t2 | ((uint32_t)t3 << 16);
                uint32_t byte = (uint32_t)(m * 512 + kc * 8) ^ ((uint32_t)(m & 7) << 4);
                *(uint2*)(sA + byte) = make_uint2(u01, u23);
            }
        }
        {
            const __nv_bfloat16* BT = (pass == 1) ? BloT : BhiT;
#pragma unroll 4
            for (int i = 0; i < 32; i++) {
                int idx = tid + i * 256;        // 0..8191 uint4 chunks
                int n = idx >> 5;
                int kc = idx & 31;              // uint4 (8 bf16) index within row
                uint4 v = *(const uint4*)&BT[n * 256 + kc * 8];
                uint32_t byte = (uint32_t)(n * 512 + kc * 16) ^ ((uint32_t)(n & 7) << 4);
                *(uint4*)(sB + byte) = v;
            }
        }
        __syncthreads();

        for (int ks = 0; ks < 16; ks++) {
            uint32_t afr[4][4], bfr[4][4];
            uint32_t kb = (uint32_t)(ks * 32);
#pragma unroll
            for (int mi = 0; mi < 4; mi++) {
                uint32_t addr = baseA + ((aoff[mi] + kb) ^ sw);
                LDSM4(afr[mi], addr);
            }
#pragma unroll
            for (int nj = 0; nj < 4; nj++) {
                uint32_t addr = baseB + ((boff[nj] + kb) ^ sw);
                LDSM4(bfr[nj], addr);
            }
#pragma unroll
            for (int mi = 0; mi < 4; mi++)
#pragma unroll
                for (int ni = 0; ni < 8; ni++) {
                    MMA16816(acc[mi][ni], afr[mi],
                             bfr[ni >> 1][(ni & 1) * 2], bfr[ni >> 1][(ni & 1) * 2 + 1]);
                }
        }
        __syncthreads();
    }

    // ---- epilogue: store C, fuse el/er = feat . al/ar per head (head == wn) ----
    float alv[16], arv[16];
#pragma unroll
    for (int ni = 0; ni < 8; ni++) {
        int col = wn * 64 + ni * 8 + 2 * (lane & 3);
        alv[ni * 2 + 0] = __ldg(&al[col]);
        alv[ni * 2 + 1] = __ldg(&al[col + 1]);
        arv[ni * 2 + 0] = __ldg(&ar[col]);
        arv[ni * 2 + 1] = __ldg(&ar[col + 1]);
    }

#pragma unroll
    for (int mi = 0; mi < 4; mi++) {
#pragma unroll
        for (int h = 0; h < 2; h++) {
            int row = r0 + wm * 64 + mi * 16 + (lane >> 2) + 8 * h;
            bool valid = row < N;
            float pl = 0.f, pr = 0.f;
#pragma unroll
            for (int ni = 0; ni < 8; ni++) {
                float c0 = acc[mi][ni][h * 2 + 0];
                float c1 = acc[mi][ni][h * 2 + 1];
                pl += c0 * alv[ni * 2] + c1 * alv[ni * 2 + 1];
                pr += c0 * arv[ni * 2] + c1 * arv[ni * 2 + 1];
                if (valid) {
                    int col = wn * 64 + ni * 8 + 2 * (lane & 3);
                    *(float2*)&C[(size_t)row * 256 + col] = make_float2(c0, c1);
                }
            }
            pl += __shfl_xor_sync(0xffffffffu, pl, 1);
            pl += __shfl_xor_sync(0xffffffffu, pl, 2);
            pr += __shfl_xor_sync(0xffffffffu, pr, 1);
            pr += __shfl_xor_sync(0xffffffffu, pr, 2);
            if (valid && (lane & 3) == 0) {
                el[row * 4 + wn] = pl;
                er[row * 4 + wn] = pr;
            }
        }
    }
}

// ---------------- small GEMM: C[N,40] = A[N,256] * B[256,40] ----------------
__global__ __launch_bounds__(256) void k_gemm40(const float* __restrict__ A,
                                                const float* __restrict__ B,
                                                float* __restrict__ C, int N) {
    __shared__ float As[128 * 33];
    __shared__ float Ws[32 * 40];

    const int tid = threadIdx.x;
    const int rg = tid >> 3;
    const int cg = tid & 7;
    const int r0 = blockIdx.x * 128;

    float acc[4][5];
#pragma unroll
    for (int i = 0; i < 4; i++)
#pragma unroll
        for (int j = 0; j < 5; j++) acc[i][j] = 0.f;

    for (int kc = 0; kc < 8; kc++) {
        __syncthreads();
#pragma unroll
        for (int i = 0; i < 4; i++) {
            int id = tid + i * 256;
            int arow = id >> 3, ac4 = id & 7;
            int grow = r0 + arow;
            float4 v = make_float4(0.f, 0.f, 0.f, 0.f);
            if (grow < N) v = *(const float4*)&A[(size_t)grow * 256 + kc * 32 + ac4 * 4];
            As[arow * 33 + ac4 * 4 + 0] = v.x;
            As[arow * 33 + ac4 * 4 + 1] = v.y;
            As[arow * 33 + ac4 * 4 + 2] = v.z;
            As[arow * 33 + ac4 * 4 + 3] = v.w;
        }
#pragma unroll
        for (int i = 0; i < 5; i++) {
            int id = tid + i * 256;
            Ws[id] = B[kc * 32 * 40 + id];
        }
        __syncthreads();
#pragma unroll
        for (int k = 0; k < 32; k++) {
            float a_[4];
#pragma unroll
            for (int i = 0; i < 4; i++) a_[i] = As[(rg * 4 + i) * 33 + k];
            float w_[5];
#pragma unroll
            for (int j = 0; j < 5; j++) w_[j] = Ws[k * 40 + cg * 5 + j];
#pragma unroll
            for (int i = 0; i < 4; i++)
#pragma unroll
                for (int j = 0; j < 5; j++) acc[i][j] += a_[i] * w_[j];
        }
    }
#pragma unroll
    for (int i = 0; i < 4; i++) {
        int r = r0 + rg * 4 + i;
        if (r < N) {
#pragma unroll
            for (int j = 0; j < 5; j++) C[r * 40 + cg * 5 + j] = acc[i][j];
        }
    }
}

// ---------------- fused aggregation + bias + ELU + LayerNorm + leaky + residual ----------------
__global__ void k_agg(const float* __restrict__ feat, const float* __restrict__ el,
                      const float* __restrict__ er, const int* __restrict__ rowptr,
                      const int* __restrict__ csr, const float* __restrict__ hin,
                      const float* __restrict__ bias, const float* __restrict__ lng,
                      const float* __restrict__ lnb, float* __restrict__ hout, int N) {
    int w = (blockIdx.x * blockDim.x + threadIdx.x) >> 5;
    int lane = threadIdx.x & 31;
    if (w >= N) return;
    int r0 = rowptr[w], r1 = rowptr[w + 1];
    int deg = r1 - r0;

    float ern0 = er[w * 4 + 0], ern1 = er[w * 4 + 1];
    float ern2 = er[w * 4 + 2], ern3 = er[w * 4 + 3];

    float m0 = -1e30f, m1 = -1e30f, m2 = -1e30f, m3 = -1e30f;
    for (int k = lane; k < deg; k += 32) {
        int s = csr[r0 + k];
        float v;
        v = el[s * 4 + 0] + ern0; v = v >= 0.f ? v : 0.2f * v; m0 = fmaxf(m0, v);
        v = el[s * 4 + 1] + ern1; v = v >= 0.f ? v : 0.2f * v; m1 = fmaxf(m1, v);
        v = el[s * 4 + 2] + ern2; v = v >= 0.f ? v : 0.2f * v; m2 = fmaxf(m2, v);
        v = el[s * 4 + 3] + ern3; v = v >= 0.f ? v : 0.2f * v; m3 = fmaxf(m3, v);
    }
#pragma unroll
    for (int o = 16; o; o >>= 1) {
        m0 = fmaxf(m0, __shfl_xor_sync(0xffffffffu, m0, o));
        m1 = fmaxf(m1, __shfl_xor_sync(0xffffffffu, m1, o));
        m2 = fmaxf(m2, __shfl_xor_sync(0xffffffffu, m2, o));
        m3 = fmaxf(m3, __shfl_xor_sync(0xffffffffu, m3, o));
    }

    int ha = lane >> 4;
    int hb = ha + 2;
    float mA = (ha == 0) ? m0 : m1;
    float mB = (ha == 0) ? m2 : m3;
    float eA = (ha == 0) ? ern0 : ern1;
    float eB = (ha == 0) ? ern2 : ern3;

    float4 a0 = make_float4(0.f, 0.f, 0.f, 0.f);
    float4 a1 = make_float4(0.f, 0.f, 0.f, 0.f);
    float sA = 0.f, sB = 0.f;
    const float4* f4 = (const float4*)feat;

    for (int k = 0; k < deg; k++) {
        int s = csr[r0 + k];
        float va = el[s * 4 + ha] + eA; va = va >= 0.f ? va : 0.2f * va;
        float vb = el[s * 4 + hb] + eB; vb = vb >= 0.f ? vb : 0.2f * vb;
        float wa = __expf(va - mA);
        float wb = __expf(vb - mB);
        sA += wa; sB += wb;
        float4 fa = f4[(size_t)s * 64 + lane];
        float4 fb = f4[(size_t)s * 64 + 32 + lane];
        a0.x += wa * fa.x; a0.y += wa * fa.y; a0.z += wa * fa.z; a0.w += wa * fa.w;
        a1.x += wb * fb.x; a1.y += wb * fb.y; a1.z += wb * fb.z; a1.w += wb * fb.w;
    }
    float iA = (sA > 0.f) ? 1.f / sA : 0.f;
    float iB = (sB > 0.f) ? 1.f / sB : 0.f;

    float x[8];
    x[0] = a0.x * iA; x[1] = a0.y * iA; x[2] = a0.z * iA; x[3] = a0.w * iA;
    x[4] = a1.x * iB; x[5] = a1.y * iB; x[6] = a1.z * iB; x[7] = a1.w * iB;

    int c0 = lane * 4;
    int c1 = 128 + lane * 4;
#pragma unroll
    for (int u = 0; u < 4; u++) {
        x[u]     += bias[c0 + u];
        x[4 + u] += bias[c1 + u];
        x[u]     = (x[u]     > 0.f) ? x[u]     : expm1f(x[u]);
        x[4 + u] = (x[4 + u] > 0.f) ? x[4 + u] : expm1f(x[4 + u]);
    }

    float sum = 0.f;
#pragma unroll
    for (int u = 0; u < 8; u++) sum += x[u];
#pragma unroll
    for (int o = 16; o; o >>= 1) sum += __shfl_xor_sync(0xffffffffu, sum, o);
    float mu = sum * (1.f / 256.f);
    float vs = 0.f;
#pragma unroll
    for (int u = 0; u < 8; u++) { float d = x[u] - mu; vs += d * d; }
#pragma unroll
    for (int o = 16; o; o >>= 1) vs += __shfl_xor_sync(0xffffffffu, vs, o);
    float rstd = rsqrtf(vs * (1.f / 256.f) + 1e-5f);

    float4 h0 = ((const float4*)hin)[(size_t)w * 64 + lane];
    float4 h1 = ((const float4*)hin)[(size_t)w * 64 + 32 + lane];
    float hr0[4] = {h0.x, h0.y, h0.z, h0.w};
    float hr1[4] = {h1.x, h1.y, h1.z, h1.w};

    float o0[4], o1[4];
#pragma unroll
    for (int u = 0; u < 4; u++) {
        float y = (x[u] - mu) * rstd * lng[c0 + u] + lnb[c0 + u];
        y = (y >= 0.f) ? y : 0.2f * y;
        o0[u] = y + hr0[u];
        float z = (x[4 + u] - mu) * rstd * lng[c1 + u] + lnb[c1 + u];
        z = (z >= 0.f) ? z : 0.2f * z;
        o1[u] = z + hr1[u];
    }
    ((float4*)hout)[(size_t)w * 64 + lane]      = make_float4(o0[0], o0[1], o0[2], o0[3]);
    ((float4*)hout)[(size_t)w * 64 + 32 + lane] = make_float4(o1[0], o1[1], o1[2], o1[3]);
}

// ---------------- output layer attention (H=1, C=40) ----------------
__global__ void k_attnO(const float* __restrict__ feat, const float* __restrict__ al,
                        const float* __restrict__ ar, float* __restrict__ el,
                        float* __restrict__ er, int N) {
    int w = (blockIdx.x * blockDim.x + threadIdx.x) >> 5;
    int lane = threadIdx.x & 31;
    if (w >= N) return;
    float pl = 0.f, pr = 0.f;
    float f = feat[w * 40 + lane];
    pl = f * al[lane];
    pr = f * ar[lane];
    if (lane < 8) {
        float f2 = feat[w * 40 + lane + 32];
        pl += f2 * al[lane + 32];
        pr += f2 * ar[lane + 32];
    }
#pragma unroll
    for (int o = 16; o; o >>= 1) {
        pl += __shfl_xor_sync(0xffffffffu, pl, o);
        pr += __shfl_xor_sync(0xffffffffu, pr, o);
    }
    if (lane == 0) { el[w] = pl; er[w] = pr; }
}

// ---------------- output aggregation -> logits [N,40] ----------------
__global__ void k_aggO(const float* __restrict__ feat, const float* __restrict__ el,
                       const float* __restrict__ er, const int* __restrict__ rowptr,
                       const int* __restrict__ csr, const float* __restrict__ bias,
                       float* __restrict__ out, int N) {
    int w = (blockIdx.x * blockDim.x + threadIdx.x) >> 5;
    int lane = threadIdx.x & 31;
    if (w >= N) return;
    int r0 = rowptr[w], r1 = rowptr[w + 1];
    int deg = r1 - r0;
    float ern = er[w];

    float m = -1e30f;
    for (int k = lane; k < deg; k += 32) {
        int s = csr[r0 + k];
        float v = el[s] + ern;
        v = v >= 0.f ? v : 0.2f * v;
        m = fmaxf(m, v);
    }
#pragma unroll
    for (int o = 16; o; o >>= 1) m = fmaxf(m, __shfl_xor_sync(0xffffffffu, m, o));

    float acc0 = 0.f, acc1 = 0.f, ss = 0.f;
    for (int k = 0; k < deg; k++) {
        int s = csr[r0 + k];
        float v = el[s] + ern;
        v = v >= 0.f ? v : 0.2f * v;
        float wgt = __expf(v - m);
        ss += wgt;
        acc0 += wgt * feat[s * 40 + lane];
        if (lane < 8) acc1 += wgt * feat[s * 40 + lane + 32];
    }
    float inv = (ss > 0.f) ? 1.f / ss : 0.f;
    out[w * 40 + lane] = acc0 * inv + bias[lane];
    if (lane < 8) out[w * 40 + lane + 32] = acc1 * inv + bias[lane + 32];
}

// ---------------- launcher ----------------
extern "C" void kernel_launch(void* const* d_in, const int* in_sizes, int n_in,
                              void* d_out, int out_size) {
    const float* x     = (const float*)d_in[0];
    const float* W_h   = (const float*)d_in[1];
    const float* al_h  = (const float*)d_in[2];
    const float* ar_h  = (const float*)d_in[3];
    const float* b_h   = (const float*)d_in[4];
    const float* lng   = (const float*)d_in[5];
    const float* lnb   = (const float*)d_in[6];
    const float* W_o   = (const float*)d_in[7];
    const float* al_o  = (const float*)d_in[8];
    const float* ar_o  = (const float*)d_in[9];
    const float* b_o   = (const float*)d_in[10];
    const int*   esrc  = (const int*)d_in[11];
    const int*   edst  = (const int*)d_in[12];
    float*       out   = (float*)d_out;

    const int N = in_sizes[0] / HID;
    const int E = in_sizes[11];

    float *feat, *bufA, *bufB, *el, *er;
    int *cnt, *rowptr, *cursor, *csr;
    __nv_bfloat16 *WhiT, *WloT;
    cudaGetSymbolAddress((void**)&feat, g_feat);
    cudaGetSymbolAddress((void**)&bufA, g_bufA);
    cudaGetSymbolAddress((void**)&bufB, g_bufB);
    cudaGetSymbolAddress((void**)&el,   g_el);
    cudaGetSymbolAddress((void**)&er,   g_er);
    cudaGetSymbolAddress((void**)&cnt,    g_cnt);
    cudaGetSymbolAddress((void**)&rowptr, g_rowptr);
    cudaGetSymbolAddress((void**)&cursor, g_cursor);
    cudaGetSymbolAddress((void**)&csr,    g_csrsrc);
    cudaGetSymbolAddress((void**)&WhiT,   g_WhiT);
    cudaGetSymbolAddress((void**)&WloT,   g_WloT);

    cudaFuncSetAttribute(k_gemmMMA, cudaFuncAttributeMaxDynamicSharedMemorySize, GEMM_SMEM);

    // --- build CSR (per call; deterministic after sort) ---
    k_zero<<<cdiv(N, 256), 256>>>(cnt, N);
    k_hist<<<cdiv(E, 256), 256>>>(edst, cnt, E);
    k_scan<<<1, 1024>>>(cnt, rowptr, cursor, N);
    k_fill<<<cdiv(E, 256), 256>>>(esrc, edst, cursor, csr, E);
    k_sortcsr<<<cdiv(N, 128), 128>>>(rowptr, csr, N);

    // --- split + transpose hidden-layer weights to bf16 hi/lo ---
    k_prepW<<<cdiv(3 * 65536, 256), 256>>>(W_h, WhiT, WloT);

    const int aggBlocks  = cdiv(N * 32, 256);
    const int gemmBlocks = cdiv(N, 128);

    const float* hcur = x;
    float* houts[3] = {bufA, bufB, bufA};
    for (int l = 0; l < 3; l++) {
        k_gemmMMA<<<gemmBlocks, 256, GEMM_SMEM>>>(hcur, WhiT + l * 65536, WloT + l * 65536,
                                                  al_h + l * 256, ar_h + l * 256,
                                                  feat, el, er, N);
        k_agg<<<aggBlocks, 256>>>(feat, el, er, rowptr, csr, hcur,
                                  b_h + l * 256, lng + l * 256, lnb + l * 256,
                                  houts[l], N);
        hcur = houts[l];
    }

    // output layer: feat40 = h @ W_o, then single-head GAT, no activation
    k_gemm40<<<cdiv(N, 128), 256>>>(hcur, W_o, feat, N);
    k_attnO<<<cdiv(N * 32, 256), 256>>>(feat, al_o, ar_o, el, er, N);
    k_aggO<<<cdiv(N * 32, 256), 256>>>(feat, el, er, rowptr, csr, b_o, out, N);
}

// round 6
// speedup vs baseline: 1.5398x; 1.0847x over previous
#include <cuda_runtime.h>
#include <cuda_fp16.h>
#include <cuda_bf16.h>
#include <math.h>
#include <stdint.h>

// Problem constants: N=100000, E=1600000, IN=HID=256, H=4, D=64, C=40
#define N_MAX 100000
#define E_MAX 1600000
#define HID   256

// ---------------- static device scratch (no allocs allowed) ----------------
__device__ __half g_feat[N_MAX * HID];   // fp16 GEMM output (also reused for 40-col output feats)
__device__ float g_bufA[N_MAX * HID];
__device__ float g_bufB[N_MAX * HID];
__device__ float g_el[N_MAX * 4];
__device__ float g_er[N_MAX * 4];
__device__ int   g_cnt[N_MAX + 1];
__device__ int   g_rowptr[N_MAX + 1];
__device__ int   g_cursor[N_MAX];
__device__ int   g_csrsrc[E_MAX];
// split-bf16 transposed weights: [3][256(n)][256(k)]
__device__ __nv_bfloat16 g_WhiT[3 * 256 * 256];
__device__ __nv_bfloat16 g_WloT[3 * 256 * 256];

static inline int cdiv(int a, int b) { return (a + b - 1) / b; }

__device__ __forceinline__ uint32_t smem_u32(const void* p) {
    uint32_t a;
    asm("{ .reg .u64 t; cvta.to.shared.u64 t, %1; cvt.u32.u64 %0, t; }" : "=r"(a) : "l"(p));
    return a;
}

#define LDSM4(r, addr)                                                          \
    asm volatile("ldmatrix.sync.aligned.m8n8.x4.shared.b16 {%0,%1,%2,%3}, [%4];" \
                 : "=r"((r)[0]), "=r"((r)[1]), "=r"((r)[2]), "=r"((r)[3])       \
                 : "r"(addr))

#define MMA16816(d, a, b0, b1)                                                  \
    asm volatile(                                                               \
        "mma.sync.aligned.m16n8k16.row.col.f32.bf16.bf16.f32 "                  \
        "{%0,%1,%2,%3}, {%4,%5,%6,%7}, {%8,%9}, {%0,%1,%2,%3};"                 \
        : "+f"((d)[0]), "+f"((d)[1]), "+f"((d)[2]), "+f"((d)[3])                \
        : "r"((a)[0]), "r"((a)[1]), "r"((a)[2]), "r"((a)[3]), "r"(b0), "r"(b1))

// ---------------- CSR build ----------------
__global__ void k_zero(int* cnt, int n) {
    int i = blockIdx.x * blockDim.x + threadIdx.x;
    if (i < n) cnt[i] = 0;
}
__global__ void k_hist(const int* __restrict__ dst, int* cnt, int E) {
    int e = blockIdx.x * blockDim.x + threadIdx.x;
    if (e < E) atomicAdd(&cnt[dst[e]], 1);
}
__global__ void k_scan(const int* __restrict__ cnt, int* rowptr, int* cursor, int N) {
    __shared__ int sm[1024];
    int t = threadIdx.x;
    int chunk = (N + 1023) >> 10;
    int s0 = t * chunk;
    int s1 = s0 + chunk; if (s1 > N) s1 = N;
    int s = 0;
    for (int i = s0; i < s1 && i < N; i++) s += cnt[i];
    sm[t] = s;
    __syncthreads();
    for (int off = 1; off < 1024; off <<= 1) {
        int v = 0;
        if (t >= off) v = sm[t - off];
        __syncthreads();
        sm[t] += v;
        __syncthreads();
    }
    int run = sm[t] - s;
    for (int i = s0; i < s1 && i < N; i++) {
        rowptr[i] = run;
        cursor[i] = run;
        run += cnt[i];
    }
    if (t == 1023) rowptr[N] = sm[1023];
}
__global__ void k_fill(const int* __restrict__ src, const int* __restrict__ dst,
                       int* cursor, int* csr, int E) {
    int e = blockIdx.x * blockDim.x + threadIdx.x;
    if (e < E) {
        int p = atomicAdd(&cursor[dst[e]], 1);
        csr[p] = src[e];
    }
}
__global__ void k_sortcsr(const int* __restrict__ rowptr, int* csr, int N) {
    int n = blockIdx.x * blockDim.x + threadIdx.x;
    if (n >= N) return;
    int a = rowptr[n], b = rowptr[n + 1];
    for (int i = a + 1; i < b; i++) {
        int v = csr[i];
        int j = i - 1;
        while (j >= a && csr[j] > v) { csr[j + 1] = csr[j]; j--; }
        csr[j + 1] = v;
    }
}

// ---------------- weight split/transpose: BT[l][n][k] = split(W[l][k][n]) ----------------
__global__ void k_prepW(const float* __restrict__ W, __nv_bfloat16* __restrict__ hiT,
                        __nv_bfloat16* __restrict__ loT) {
    int i = blockIdx.x * blockDim.x + threadIdx.x;
    if (i >= 3 * 65536) return;
    int l = i >> 16, r = i & 65535;
    int n = r >> 8, k = r & 255;
    float w = W[l * 65536 + k * 256 + n];
    __nv_bfloat16 h = __float2bfloat16(w);
    hiT[i] = h;
    loT[i] = __float2bfloat16(w - __bfloat162float(h));
}

// ---------------- split-bf16 mma.sync GEMM + fused attn-coefficient epilogue -------------
// feat(fp16)[128 x 256] = A[128 x 256] @ W ;  el/er = feat . al/ar per head.
#define GEMM_SMEM (65536 + 131072)

__global__ __launch_bounds__(256, 1)
void k_gemmMMA(const float* __restrict__ A,
               const __nv_bfloat16* __restrict__ BhiT,
               const __nv_bfloat16* __restrict__ BloT,
               const float* __restrict__ al, const float* __restrict__ ar,
               __half* __restrict__ C, float* __restrict__ el, float* __restrict__ er,
               int N) {
    extern __shared__ __align__(128) char smem[];
    char* sA = smem;            // 64KB: [m(128)][k(256)] bf16, row 512B, swizzled
    char* sB = smem + 65536;    // 128KB: [n(256)][k(256)] bf16, row 512B, swizzled

    const int tid  = threadIdx.x;
    const int lane = tid & 31;
    const int wid  = tid >> 5;
    const int wm   = wid >> 2;
    const int wn   = wid & 3;    // head
    const int r0   = blockIdx.x * 128;

    const uint32_t baseA = smem_u32(sA);
    const uint32_t baseB = smem_u32(sB);
    const uint32_t sw = (uint32_t)(lane & 7) << 4;

    float acc[4][8][4];
#pragma unroll
    for (int mi = 0; mi < 4; mi++)
#pragma unroll
        for (int ni = 0; ni < 8; ni++)
#pragma unroll
            for (int q = 0; q < 4; q++) acc[mi][ni][q] = 0.f;

    uint32_t aoff[4], boff[4];
#pragma unroll
    for (int mi = 0; mi < 4; mi++) {
        int m = wm * 64 + mi * 16 + (lane & 15);
        aoff[mi] = (uint32_t)(m * 512 + ((lane >> 4) << 4));
    }
#pragma unroll
    for (int nj = 0; nj < 4; nj++) {
        int n = wn * 64 + nj * 16 + (lane & 7) + ((lane >> 4) << 3);
        boff[nj] = (uint32_t)(n * 512 + (((lane >> 3) & 1) << 4));
    }

    for (int pass = 0; pass < 3; pass++) {
        if (pass != 1) {
            const bool lo = (pass == 2);
#pragma unroll 4
            for (int i = 0; i < 32; i++) {
                int idx = tid + i * 256;
                int m = idx >> 6;
                int kc = idx & 63;
                int rowG = r0 + m;
                float4 v = make_float4(0.f, 0.f, 0.f, 0.f);
                if (rowG < N) v = *(const float4*)&A[(size_t)rowG * 256 + kc * 4];
                unsigned short t0, t1, t2, t3;
                if (!lo) {
                    t0 = __bfloat16_as_ushort(__float2bfloat16(v.x));
                    t1 = __bfloat16_as_ushort(__float2bfloat16(v.y));
                    t2 = __bfloat16_as_ushort(__float2bfloat16(v.z));
                    t3 = __bfloat16_as_ushort(__float2bfloat16(v.w));
                } else {
                    __nv_bfloat16 h;
                    h = __float2bfloat16(v.x); t0 = __bfloat16_as_ushort(__float2bfloat16(v.x - __bfloat162float(h)));
                    h = __float2bfloat16(v.y); t1 = __bfloat16_as_ushort(__float2bfloat16(v.y - __bfloat162float(h)));
                    h = __float2bfloat16(v.z); t2 = __bfloat16_as_ushort(__float2bfloat16(v.z - __bfloat162float(h)));
                    h = __float2bfloat16(v.w); t3 = __bfloat16_as_ushort(__float2bfloat16(v.w - __bfloat162float(h)));
                }
                uint32_t u01 = (uint32_t)t0 | ((uint32_t)t1 << 16);
                uint32_t u23 = (uint32_t)t2 | ((uint32_t)t3 << 16);
                uint32_t byte = (uint32_t)(m * 512 + kc * 8) ^ ((uint32_t)(m & 7) << 4);
                *(uint2*)(sA + byte) = make_uint2(u01, u23);
            }
        }
        {
            const __nv_bfloat16* BT = (pass == 1) ? BloT : BhiT;
#pragma unroll 4
            for (int i = 0; i < 32; i++) {
                int idx = tid + i * 256;
                int n = idx >> 5;
                int kc = idx & 31;
                uint4 v = *(const uint4*)&BT[n * 256 + kc * 8];
                uint32_t byte = (uint32_t)(n * 512 + kc * 16) ^ ((uint32_t)(n & 7) << 4);
                *(uint4*)(sB + byte) = v;
            }
        }
        __syncthreads();

        for (int ks = 0; ks < 16; ks++) {
            uint32_t afr[4][4], bfr[4][4];
            uint32_t kb = (uint32_t)(ks * 32);
#pragma unroll
            for (int mi = 0; mi < 4; mi++) {
                uint32_t addr = baseA + ((aoff[mi] + kb) ^ sw);
                LDSM4(afr[mi], addr);
            }
#pragma unroll
            for (int nj = 0; nj < 4; nj++) {
                uint32_t addr = baseB + ((boff[nj] + kb) ^ sw);
                LDSM4(bfr[nj], addr);
            }
#pragma unroll
            for (int mi = 0; mi < 4; mi++)
#pragma unroll
                for (int ni = 0; ni < 8; ni++) {
                    MMA16816(acc[mi][ni], afr[mi],
                             bfr[ni >> 1][(ni & 1) * 2], bfr[ni >> 1][(ni & 1) * 2 + 1]);
                }
        }
        __syncthreads();
    }

    // ---- epilogue: store fp16 feat, fuse el/er per head (head == wn) ----
    float alv[16], arv[16];
#pragma unroll
    for (int ni = 0; ni < 8; ni++) {
        int col = wn * 64 + ni * 8 + 2 * (lane & 3);
        alv[ni * 2 + 0] = __ldg(&al[col]);
        alv[ni * 2 + 1] = __ldg(&al[col + 1]);
        arv[ni * 2 + 0] = __ldg(&ar[col]);
        arv[ni * 2 + 1] = __ldg(&ar[col + 1]);
    }

#pragma unroll
    for (int mi = 0; mi < 4; mi++) {
#pragma unroll
        for (int h = 0; h < 2; h++) {
            int row = r0 + wm * 64 + mi * 16 + (lane >> 2) + 8 * h;
            bool valid = row < N;
            float pl = 0.f, pr = 0.f;
#pragma unroll
            for (int ni = 0; ni < 8; ni++) {
                float c0 = acc[mi][ni][h * 2 + 0];
                float c1 = acc[mi][ni][h * 2 + 1];
                pl += c0 * alv[ni * 2] + c1 * alv[ni * 2 + 1];
                pr += c0 * arv[ni * 2] + c1 * arv[ni * 2 + 1];
                if (valid) {
                    int col = wn * 64 + ni * 8 + 2 * (lane & 3);
                    *(__half2*)&C[(size_t)row * 256 + col] =
                        __floats2half2_rn(c0, c1);
                }
            }
            pl += __shfl_xor_sync(0xffffffffu, pl, 1);
            pl += __shfl_xor_sync(0xffffffffu, pl, 2);
            pr += __shfl_xor_sync(0xffffffffu, pr, 1);
            pr += __shfl_xor_sync(0xffffffffu, pr, 2);
            if (valid && (lane & 3) == 0) {
                el[row * 4 + wn] = pl;
                er[row * 4 + wn] = pr;
            }
        }
    }
}

// ---------------- small GEMM + fused output attn: C16[N,40], el/er[N] ----------------
__global__ __launch_bounds__(256) void k_gemm40(const float* __restrict__ A,
                                                const float* __restrict__ B,
                                                const float* __restrict__ al,
                                                const float* __restrict__ ar,
                                                __half* __restrict__ C,
                                                float* __restrict__ el,
                                                float* __restrict__ er, int N) {
    __shared__ float As[128 * 33];
    __shared__ float Ws[32 * 40];

    const int tid = threadIdx.x;
    const int rg = tid >> 3;
    const int cg = tid & 7;
    const int r0 = blockIdx.x * 128;

    float acc[4][5];
#pragma unroll
    for (int i = 0; i < 4; i++)
#pragma unroll
        for (int j = 0; j < 5; j++) acc[i][j] = 0.f;

    for (int kc = 0; kc < 8; kc++) {
        __syncthreads();
#pragma unroll
        for (int i = 0; i < 4; i++) {
            int id = tid + i * 256;
            int arow = id >> 3, ac4 = id & 7;
            int grow = r0 + arow;
            float4 v = make_float4(0.f, 0.f, 0.f, 0.f);
            if (grow < N) v = *(const float4*)&A[(size_t)grow * 256 + kc * 32 + ac4 * 4];
            As[arow * 33 + ac4 * 4 + 0] = v.x;
            As[arow * 33 + ac4 * 4 + 1] = v.y;
            As[arow * 33 + ac4 * 4 + 2] = v.z;
            As[arow * 33 + ac4 * 4 + 3] = v.w;
        }
#pragma unroll
        for (int i = 0; i < 5; i++) {
            int id = tid + i * 256;
            Ws[id] = B[kc * 32 * 40 + id];
        }
        __syncthreads();
#pragma unroll
        for (int k = 0; k < 32; k++) {
            float a_[4];
#pragma unroll
            for (int i = 0; i < 4; i++) a_[i] = As[(rg * 4 + i) * 33 + k];
            float w_[5];
#pragma unroll
            for (int j = 0; j < 5; j++) w_[j] = Ws[k * 40 + cg * 5 + j];
#pragma unroll
            for (int i = 0; i < 4; i++)
#pragma unroll
                for (int j = 0; j < 5; j++) acc[i][j] += a_[i] * w_[j];
        }
    }

    float alv[5], arv[5];
#pragma unroll
    for (int j = 0; j < 5; j++) {
        alv[j] = __ldg(&al[cg * 5 + j]);
        arv[j] = __ldg(&ar[cg * 5 + j]);
    }
#pragma unroll
    for (int i = 0; i < 4; i++) {
        int r = r0 + rg * 4 + i;
        float pl = 0.f, pr = 0.f;
#pragma unroll
        for (int j = 0; j < 5; j++) {
            pl += acc[i][j] * alv[j];
            pr += acc[i][j] * arv[j];
        }
        pl += __shfl_xor_sync(0xffffffffu, pl, 1);
        pl += __shfl_xor_sync(0xffffffffu, pl, 2);
        pl += __shfl_xor_sync(0xffffffffu, pl, 4);
        pr += __shfl_xor_sync(0xffffffffu, pr, 1);
        pr += __shfl_xor_sync(0xffffffffu, pr, 2);
        pr += __shfl_xor_sync(0xffffffffu, pr, 4);
        if (r < N) {
#pragma unroll
            for (int j = 0; j < 5; j++) C[(size_t)r * 40 + cg * 5 + j] = __float2half(acc[i][j]);
            if (cg == 0) { el[r] = pl; er[r] = pr; }
        }
    }
}

// ---------------- fused aggregation + bias + ELU + LayerNorm + leaky + residual ----------------
// one warp per destination node; lane owns 8 channels [lane*8, lane*8+8) of head lane>>3
__global__ void k_agg(const __half* __restrict__ feat, const float* __restrict__ el,
                      const float* __restrict__ er, const int* __restrict__ rowptr,
                      const int* __restrict__ csr, const float* __restrict__ hin,
                      const float* __restrict__ bias, const float* __restrict__ lng,
                      const float* __restrict__ lnb, float* __restrict__ hout, int N) {
    int w = (blockIdx.x * blockDim.x + threadIdx.x) >> 5;
    int lane = threadIdx.x & 31;
    if (w >= N) return;
    int r0 = rowptr[w], r1 = rowptr[w + 1];
    int deg = r1 - r0;
    int h = lane >> 3;                        // this lane's head
    float ern = er[w * 4 + h];

    float acc[8];
#pragma unroll
    for (int u = 0; u < 8; u++) acc[u] = 0.f;
    float sA = 0.f;

    int sN = (deg > 0) ? csr[r0] : 0;
    for (int k = 0; k < deg; k++) {
        int s = sN;
        if (k + 1 < deg) sN = csr[r0 + k + 1];
        float e = __ldg(&el[s * 4 + h]) + ern;
        e = (e >= 0.f) ? e : 0.2f * e;
        float wgt = __expf(e);                // no max shift: |e| bounded small
        sA += wgt;
        uint4 f = __ldg((const uint4*)(feat + (size_t)s * 256) + lane);
        const __half2* hp = (const __half2*)&f;
#pragma unroll
        for (int u = 0; u < 4; u++) {
            float2 v = __half22float2(hp[u]);
            acc[2 * u + 0] += wgt * v.x;
            acc[2 * u + 1] += wgt * v.y;
        }
    }
    float inv = (sA > 0.f) ? 1.f / sA : 0.f;

    float x[8];
    int c0 = lane * 8;
#pragma unroll
    for (int u = 0; u < 8; u++) {
        x[u] = acc[u] * inv + bias[c0 + u];
        x[u] = (x[u] > 0.f) ? x[u] : expm1f(x[u]);
    }

    // LayerNorm over 256 channels (8 per lane)
    float sum = 0.f;
#pragma unroll
    for (int u = 0; u < 8; u++) sum += x[u];
#pragma unroll
    for (int o = 16; o; o >>= 1) sum += __shfl_xor_sync(0xffffffffu, sum, o);
    float mu = sum * (1.f / 256.f);
    float vs = 0.f;
#pragma unroll
    for (int u = 0; u < 8; u++) { float d = x[u] - mu; vs += d * d; }
#pragma unroll
    for (int o = 16; o; o >>= 1) vs += __shfl_xor_sync(0xffffffffu, vs, o);
    float rstd = rsqrtf(vs * (1.f / 256.f) + 1e-5f);

    float4 h0 = ((const float4*)hin)[(size_t)w * 64 + lane * 2];
    float4 h1 = ((const float4*)hin)[(size_t)w * 64 + lane * 2 + 1];
    float hr[8] = {h0.x, h0.y, h0.z, h0.w, h1.x, h1.y, h1.z, h1.w};

    float o0[8];
#pragma unroll
    for (int u = 0; u < 8; u++) {
        float y = (x[u] - mu) * rstd * lng[c0 + u] + lnb[c0 + u];
        y = (y >= 0.f) ? y : 0.2f * y;
        o0[u] = y + hr[u];
    }
    ((float4*)hout)[(size_t)w * 64 + lane * 2]     = make_float4(o0[0], o0[1], o0[2], o0[3]);
    ((float4*)hout)[(size_t)w * 64 + lane * 2 + 1] = make_float4(o0[4], o0[5], o0[6], o0[7]);
}

// ---------------- output aggregation -> logits [N,40] ----------------
__global__ void k_aggO(const __half* __restrict__ feat, const float* __restrict__ el,
                       const float* __restrict__ er, const int* __restrict__ rowptr,
                       const int* __restrict__ csr, const float* __restrict__ bias,
                       float* __restrict__ out, int N) {
    int w = (blockIdx.x * blockDim.x + threadIdx.x) >> 5;
    int lane = threadIdx.x & 31;
    if (w >= N) return;
    int r0 = rowptr[w], r1 = rowptr[w + 1];
    int deg = r1 - r0;
    float ern = er[w];

    float acc0 = 0.f, acc1 = 0.f, ss = 0.f;
    int sN = (deg > 0) ? csr[r0] : 0;
    for (int k = 0; k < deg; k++) {
        int s = sN;
        if (k + 1 < deg) sN = csr[r0 + k + 1];
        float e = __ldg(&el[s]) + ern;
        e = (e >= 0.f) ? e : 0.2f * e;
        float wgt = __expf(e);
        ss += wgt;
        if (lane < 20) {
            __half2 f = __ldg((const __half2*)(feat + (size_t)s * 40) + lane);
            float2 v = __half22float2(f);
            acc0 += wgt * v.x;
            acc1 += wgt * v.y;
        }
    }
    float inv = (ss > 0.f) ? 1.f / ss : 0.f;
    if (lane < 20) {
        out[(size_t)w * 40 + 2 * lane]     = acc0 * inv + bias[2 * lane];
        out[(size_t)w * 40 + 2 * lane + 1] = acc1 * inv + bias[2 * lane + 1];
    }
}

// ---------------- launcher ----------------
extern "C" void kernel_launch(void* const* d_in, const int* in_sizes, int n_in,
                              void* d_out, int out_size) {
    const float* x     = (const float*)d_in[0];
    const float* W_h   = (const float*)d_in[1];
    const float* al_h  = (const float*)d_in[2];
    const float* ar_h  = (const float*)d_in[3];
    const float* b_h   = (const float*)d_in[4];
    const float* lng   = (const float*)d_in[5];
    const float* lnb   = (const float*)d_in[6];
    const float* W_o   = (const float*)d_in[7];
    const float* al_o  = (const float*)d_in[8];
    const float* ar_o  = (const float*)d_in[9];
    const float* b_o   = (const float*)d_in[10];
    const int*   esrc  = (const int*)d_in[11];
    const int*   edst  = (const int*)d_in[12];
    float*       out   = (float*)d_out;

    const int N = in_sizes[0] / HID;
    const int E = in_sizes[11];

    float *bufA, *bufB, *el, *er;
    __half* feat;
    int *cnt, *rowptr, *cursor, *csr;
    __nv_bfloat16 *WhiT, *WloT;
    cudaGetSymbolAddress((void**)&feat, g_feat);
    cudaGetSymbolAddress((void**)&bufA, g_bufA);
    cudaGetSymbolAddress((void**)&bufB, g_bufB);
    cudaGetSymbolAddress((void**)&el,   g_el);
    cudaGetSymbolAddress((void**)&er,   g_er);
    cudaGetSymbolAddress((void**)&cnt,    g_cnt);
    cudaGetSymbolAddress((void**)&rowptr, g_rowptr);
    cudaGetSymbolAddress((void**)&cursor, g_cursor);
    cudaGetSymbolAddress((void**)&csr,    g_csrsrc);
    cudaGetSymbolAddress((void**)&WhiT,   g_WhiT);
    cudaGetSymbolAddress((void**)&WloT,   g_WloT);

    cudaFuncSetAttribute(k_gemmMMA, cudaFuncAttributeMaxDynamicSharedMemorySize, GEMM_SMEM);

    // --- build CSR (per call; deterministic after sort) ---
    k_zero<<<cdiv(N, 256), 256>>>(cnt, N);
    k_hist<<<cdiv(E, 256), 256>>>(edst, cnt, E);
    k_scan<<<1, 1024>>>(cnt, rowptr, cursor, N);
    k_fill<<<cdiv(E, 256), 256>>>(esrc, edst, cursor, csr, E);
    k_sortcsr<<<cdiv(N, 128), 128>>>(rowptr, csr, N);

    // --- split + transpose hidden-layer weights to bf16 hi/lo ---
    k_prepW<<<cdiv(3 * 65536, 256), 256>>>(W_h, WhiT, WloT);

    const int aggBlocks  = cdiv(N * 32, 256);
    const int gemmBlocks = cdiv(N, 128);

    const float* hcur = x;
    float* houts[3] = {bufA, bufB, bufA};
    for (int l = 0; l < 3; l++) {
        k_gemmMMA<<<gemmBlocks, 256, GEMM_SMEM>>>(hcur, WhiT + l * 65536, WloT + l * 65536,
                                                  al_h + l * 256, ar_h + l * 256,
                                                  feat, el, er, N);
        k_agg<<<aggBlocks, 256>>>(feat, el, er, rowptr, csr, hcur,
                                  b_h + l * 256, lng + l * 256, lnb + l * 256,
                                  houts[l], N);
        hcur = houts[l];
    }

    // output layer: feat40(fp16) = h @ W_o with fused attn, then single-head GAT
    k_gemm40<<<cdiv(N, 128), 256>>>(hcur, W_o, al_o, ar_o, feat, el, er, N);
    k_aggO<<<cdiv(N * 32, 256), 256>>>(feat, el, er, rowptr, csr, b_o, out, N);
}